// round 2
// baseline (speedup 1.0000x reference)
#include <cuda_runtime.h>
#include <cuda_fp16.h>
#include <cstdint>

// ---------------------------------------------------------------------------
// BitLinear: out[m,n] = scale[n] * sum_k xh[m,k] * wq[n,k]
//   xh  = fp16(x)                  [8192, 2048]
//   wq  = ternary {-1,0,1} fp16    [8192, 2048]
//   out = fp32                     [8192, 8192]
//
// tcgen05 is NOT available (harness PTX target is plain sm_103, no 'a').
// GEMM uses mma.sync.m16n8k16 (HMMA) + cp.async 4-stage pipeline.
// ---------------------------------------------------------------------------

#define M_TOT 8192
#define N_TOT 8192
#define K_TOT 2048

#define BM 128
#define BN 128
#define BK 32
#define STAGES 4
#define NUM_CHUNKS (K_TOT / BK)      // 64

// padded smem row stride: 40 halves = 80 bytes (bank-conflict free)
#define SROW 40
#define STILE_BYTES (BM * SROW * 2)  // 10240 per tile per stage
#define SMEM_A_OFF(s) ((s) * STILE_BYTES)
#define SMEM_B_OFF(s) (STAGES * STILE_BYTES + (s) * STILE_BYTES)
#define SMEM_TOTAL (2 * STAGES * STILE_BYTES)   // 81920

__device__ __half g_Xh[(size_t)M_TOT * K_TOT];
__device__ __half g_Wq[(size_t)N_TOT * K_TOT];
__device__ float  g_scale[N_TOT];

// ------------------------------ helpers ------------------------------------
__device__ __forceinline__ uint32_t smem_u32(const void* p) {
    uint32_t a;
    asm("{ .reg .u64 t; cvta.to.shared.u64 t, %1; cvt.u32.u64 %0, t; }"
        : "=r"(a) : "l"(p));
    return a;
}

__device__ __forceinline__ void cp_async16(uint32_t dst, const void* src) {
    asm volatile("cp.async.cg.shared.global [%0], [%1], 16;"
                 :: "r"(dst), "l"(src));
}

__device__ __forceinline__ void ldsm_x4(uint32_t addr, uint32_t* r) {
    asm volatile("ldmatrix.sync.aligned.m8n8.x4.shared.b16 {%0,%1,%2,%3}, [%4];"
                 : "=r"(r[0]), "=r"(r[1]), "=r"(r[2]), "=r"(r[3]) : "r"(addr));
}

__device__ __forceinline__ void mma16816(float* c, const uint32_t* a,
                                         uint32_t b0, uint32_t b1) {
    asm volatile(
        "mma.sync.aligned.m16n8k16.row.col.f32.f16.f16.f32 "
        "{%0,%1,%2,%3}, {%4,%5,%6,%7}, {%8,%9}, {%0,%1,%2,%3};"
        : "+f"(c[0]), "+f"(c[1]), "+f"(c[2]), "+f"(c[3])
        : "r"(a[0]), "r"(a[1]), "r"(a[2]), "r"(a[3]), "r"(b0), "r"(b1));
}

// ------------------------------ prep kernels -------------------------------
__global__ void convert_x_kernel(const float* __restrict__ x) {
    size_t i = (size_t)blockIdx.x * blockDim.x + threadIdx.x; // 8 elems each
    const float4* X4 = reinterpret_cast<const float4*>(x);
    float4 a = X4[2 * i];
    float4 b = X4[2 * i + 1];
    __half2 h0 = __floats2half2_rn(a.x, a.y);
    __half2 h1 = __floats2half2_rn(a.z, a.w);
    __half2 h2 = __floats2half2_rn(b.x, b.y);
    __half2 h3 = __floats2half2_rn(b.z, b.w);
    uint4 o;
    o.x = *reinterpret_cast<uint32_t*>(&h0);
    o.y = *reinterpret_cast<uint32_t*>(&h1);
    o.z = *reinterpret_cast<uint32_t*>(&h2);
    o.w = *reinterpret_cast<uint32_t*>(&h3);
    reinterpret_cast<uint4*>(g_Xh)[i] = o;
}

__global__ void quantize_w_kernel(const float* __restrict__ W) {
    const int row = blockIdx.x;
    const int tid = threadIdx.x;
    const float* wr = W + (size_t)row * K_TOT;

    const int base = tid * 8;                        // 256 * 8 = 2048
    float4 a = *reinterpret_cast<const float4*>(wr + base);
    float4 b = *reinterpret_cast<const float4*>(wr + base + 4);
    float s = fabsf(a.x) + fabsf(a.y) + fabsf(a.z) + fabsf(a.w) +
              fabsf(b.x) + fabsf(b.y) + fabsf(b.z) + fabsf(b.w);
    #pragma unroll
    for (int o = 16; o; o >>= 1) s += __shfl_xor_sync(0xFFFFFFFFu, s, o);

    __shared__ float warp_s[8];
    __shared__ float s_scale;
    if ((tid & 31) == 0) warp_s[tid >> 5] = s;
    __syncthreads();
    if (tid == 0) {
        float t = 0.f;
        #pragma unroll
        for (int i = 0; i < 8; i++) t += warp_s[i];
        float sc = t * (1.0f / 2048.0f);
        if (sc < 1e-5f) sc = 1e-5f;
        g_scale[row] = sc;
        s_scale = sc;
    }
    __syncthreads();
    const float sc = s_scale;

    float v[8] = {a.x, a.y, a.z, a.w, b.x, b.y, b.z, b.w};
    __half q[8];
    #pragma unroll
    for (int i = 0; i < 8; i++) {
        float t = rintf(v[i] / sc);              // matches jnp.round
        t = fmaxf(-1.f, fminf(1.f, t));
        q[i] = __float2half_rn(t);
    }
    *reinterpret_cast<uint4*>(g_Wq + (size_t)row * K_TOT + base) =
        *reinterpret_cast<uint4*>(q);
}

// ------------------------------ GEMM kernel --------------------------------
__global__ void __launch_bounds__(256, 2)
bitlinear_gemm(float* __restrict__ out) {
    extern __shared__ char smem[];
    const uint32_t sbase = smem_u32(smem);
    const int tid    = threadIdx.x;
    const int wid    = tid >> 5;
    const int lane   = tid & 31;
    const int warp_m = wid & 1;       // 2 warps along M
    const int warp_n = wid >> 1;      // 4 warps along N
    const int m0 = blockIdx.y * BM;
    const int n0 = blockIdx.x * BN;

    const __half* Ag = g_Xh + (size_t)m0 * K_TOT;
    const __half* Bg = g_Wq + (size_t)n0 * K_TOT;

    // copy mapping: 512 16B-segments per tile; thread does 2 per tile
    const int seg0 = tid, seg1 = tid + 256;
    const int r0c = seg0 >> 2, s0c = seg0 & 3;
    const int r1c = seg1 >> 2, s1c = seg1 & 3;

    auto issue_copy = [&](int stage, int chunk) {
        const int k0 = chunk * BK;
        uint32_t da = sbase + SMEM_A_OFF(stage);
        uint32_t db = sbase + SMEM_B_OFF(stage);
        cp_async16(da + r0c * 80 + s0c * 16, Ag + (size_t)r0c * K_TOT + k0 + s0c * 8);
        cp_async16(da + r1c * 80 + s1c * 16, Ag + (size_t)r1c * K_TOT + k0 + s1c * 8);
        cp_async16(db + r0c * 80 + s0c * 16, Bg + (size_t)r0c * K_TOT + k0 + s0c * 8);
        cp_async16(db + r1c * 80 + s1c * 16, Bg + (size_t)r1c * K_TOT + k0 + s1c * 8);
    };

    // ldmatrix per-thread address components
    const int aRow = warp_m * 64 + (lane & 15);        // + mt*16
    const int aCol = (lane >> 4) * 8;                  // + ks*16
    const int g    = lane >> 3;
    const int bRow = warp_n * 32 + ((g >> 1) << 3) + (lane & 7);  // + nt*16
    const int bCol = (g & 1) * 8;                      // + ks*16

    float acc[4][4][4];
    #pragma unroll
    for (int i = 0; i < 4; i++)
        #pragma unroll
        for (int j = 0; j < 4; j++)
            #pragma unroll
            for (int t = 0; t < 4; t++) acc[i][j][t] = 0.f;

    // prologue: stages 0..2
    #pragma unroll
    for (int s = 0; s < STAGES - 1; s++) {
        issue_copy(s, s);
        asm volatile("cp.async.commit_group;");
    }

    for (int c = 0; c < NUM_CHUNKS; c++) {
        asm volatile("cp.async.wait_group %0;" :: "n"(STAGES - 2));
        __syncthreads();

        const int nc = c + STAGES - 1;
        if (nc < NUM_CHUNKS) issue_copy(nc % STAGES, nc);
        asm volatile("cp.async.commit_group;");

        const int st = c % STAGES;
        const uint32_t sa = sbase + SMEM_A_OFF(st);
        const uint32_t sb = sbase + SMEM_B_OFF(st);

        #pragma unroll
        for (int ks = 0; ks < 2; ks++) {
            uint32_t af[4][4];
            #pragma unroll
            for (int mt = 0; mt < 4; mt++)
                ldsm_x4(sa + (aRow + mt * 16) * 80 + (aCol + ks * 16) * 2, af[mt]);
            uint32_t bf[2][4];
            #pragma unroll
            for (int nt = 0; nt < 2; nt++)
                ldsm_x4(sb + (bRow + nt * 16) * 80 + (bCol + ks * 16) * 2, bf[nt]);
            #pragma unroll
            for (int mi = 0; mi < 4; mi++)
                #pragma unroll
                for (int ni = 0; ni < 4; ni++)
                    mma16816(acc[mi][ni], af[mi],
                             bf[ni >> 1][(ni & 1) * 2],
                             bf[ni >> 1][(ni & 1) * 2 + 1]);
        }
    }

    // ---------------- epilogue: scale by g_scale[n], store fp32 ------------
    const int q = lane >> 2;          // row-in-8
    const int t = lane & 3;           // col-pair
    #pragma unroll
    for (int ni = 0; ni < 4; ni++) {
        const int n = n0 + warp_n * 32 + ni * 8 + t * 2;
        const float2 sc = *reinterpret_cast<const float2*>(&g_scale[n]);
        #pragma unroll
        for (int mi = 0; mi < 4; mi++) {
            const int m = m0 + warp_m * 64 + mi * 16 + q;
            float2 v0 = make_float2(acc[mi][ni][0] * sc.x, acc[mi][ni][1] * sc.y);
            float2 v1 = make_float2(acc[mi][ni][2] * sc.x, acc[mi][ni][3] * sc.y);
            *reinterpret_cast<float2*>(out + (size_t)m * N_TOT + n) = v0;
            *reinterpret_cast<float2*>(out + (size_t)(m + 8) * N_TOT + n) = v1;
        }
    }
}

// ------------------------------ launch -------------------------------------
extern "C" void kernel_launch(void* const* d_in, const int* in_sizes, int n_in,
                              void* d_out, int out_size) {
    const float* x = (const float*)d_in[0];      // [4,2048,2048]
    const float* w = (const float*)d_in[1];      // [8192,2048]
    float* out = (float*)d_out;                  // [4,2048,8192]

    cudaFuncSetAttribute(bitlinear_gemm,
                         cudaFuncAttributeMaxDynamicSharedMemorySize,
                         SMEM_TOTAL);

    convert_x_kernel<<<(M_TOT * K_TOT) / (256 * 8), 256>>>(x);
    quantize_w_kernel<<<N_TOT, 256>>>(w);

    dim3 grid(N_TOT / BN, M_TOT / BM);
    bitlinear_gemm<<<grid, 256, SMEM_TOTAL>>>(out);
}

// round 3
// speedup vs baseline: 1.0772x; 1.0772x over previous
#include <cuda_runtime.h>
#include <cuda_fp16.h>
#include <cstdint>

// ---------------------------------------------------------------------------
// BitLinear: out[m,n] = scale[n] * sum_k xh[m,k] * wq[n,k]
//   xh  = fp16(x)                  [8192, 2048]
//   wq  = ternary {-1,0,1} fp16    [8192, 2048]
//   out = fp32                     [8192, 8192]
//
// mma.sync.m16n8k16 (HMMA) + cp.async, BK=64, 3-stage pipeline, 2 CTAs/SM.
// ---------------------------------------------------------------------------

#define M_TOT 8192
#define N_TOT 8192
#define K_TOT 2048

#define BM 128
#define BN 128
#define BK 64
#define STAGES 3
#define NUM_CHUNKS (K_TOT / BK)      // 32

// smem row: 64 halves + 8 pad = 72 halves = 144 bytes
#define SROWB 144
#define STILE_BYTES (BM * SROWB)     // 18432
#define SMEM_A_OFF(s) ((s) * STILE_BYTES)
#define SMEM_B_OFF(s) (STAGES * STILE_BYTES + (s) * STILE_BYTES)
#define SMEM_TOTAL (2 * STAGES * STILE_BYTES)   // 110592

__device__ __half g_Xh[(size_t)M_TOT * K_TOT];
__device__ __half g_Wq[(size_t)N_TOT * K_TOT];
__device__ float  g_scale[N_TOT];

// ------------------------------ helpers ------------------------------------
__device__ __forceinline__ uint32_t smem_u32(const void* p) {
    uint32_t a;
    asm("{ .reg .u64 t; cvta.to.shared.u64 t, %1; cvt.u32.u64 %0, t; }"
        : "=r"(a) : "l"(p));
    return a;
}

__device__ __forceinline__ void cp_async16(uint32_t dst, const void* src) {
    asm volatile("cp.async.cg.shared.global [%0], [%1], 16;"
                 :: "r"(dst), "l"(src));
}

__device__ __forceinline__ void ldsm_x4(uint32_t addr, uint32_t* r) {
    asm volatile("ldmatrix.sync.aligned.m8n8.x4.shared.b16 {%0,%1,%2,%3}, [%4];"
                 : "=r"(r[0]), "=r"(r[1]), "=r"(r[2]), "=r"(r[3]) : "r"(addr));
}

__device__ __forceinline__ void mma16816(float* c, const uint32_t* a,
                                         uint32_t b0, uint32_t b1) {
    asm volatile(
        "mma.sync.aligned.m16n8k16.row.col.f32.f16.f16.f32 "
        "{%0,%1,%2,%3}, {%4,%5,%6,%7}, {%8,%9}, {%0,%1,%2,%3};"
        : "+f"(c[0]), "+f"(c[1]), "+f"(c[2]), "+f"(c[3])
        : "r"(a[0]), "r"(a[1]), "r"(a[2]), "r"(a[3]), "r"(b0), "r"(b1));
}

// ------------------------------ prep kernels -------------------------------
__global__ void convert_x_kernel(const float* __restrict__ x) {
    size_t i = (size_t)blockIdx.x * blockDim.x + threadIdx.x; // 8 elems each
    const float4* X4 = reinterpret_cast<const float4*>(x);
    float4 a = X4[2 * i];
    float4 b = X4[2 * i + 1];
    __half2 h0 = __floats2half2_rn(a.x, a.y);
    __half2 h1 = __floats2half2_rn(a.z, a.w);
    __half2 h2 = __floats2half2_rn(b.x, b.y);
    __half2 h3 = __floats2half2_rn(b.z, b.w);
    uint4 o;
    o.x = *reinterpret_cast<uint32_t*>(&h0);
    o.y = *reinterpret_cast<uint32_t*>(&h1);
    o.z = *reinterpret_cast<uint32_t*>(&h2);
    o.w = *reinterpret_cast<uint32_t*>(&h3);
    reinterpret_cast<uint4*>(g_Xh)[i] = o;
}

__global__ void quantize_w_kernel(const float* __restrict__ W) {
    const int row = blockIdx.x;
    const int tid = threadIdx.x;
    const float* wr = W + (size_t)row * K_TOT;

    const int base = tid * 8;                        // 256 * 8 = 2048
    float4 a = *reinterpret_cast<const float4*>(wr + base);
    float4 b = *reinterpret_cast<const float4*>(wr + base + 4);
    float s = fabsf(a.x) + fabsf(a.y) + fabsf(a.z) + fabsf(a.w) +
              fabsf(b.x) + fabsf(b.y) + fabsf(b.z) + fabsf(b.w);
    #pragma unroll
    for (int o = 16; o; o >>= 1) s += __shfl_xor_sync(0xFFFFFFFFu, s, o);

    __shared__ float warp_s[8];
    __shared__ float s_scale;
    if ((tid & 31) == 0) warp_s[tid >> 5] = s;
    __syncthreads();
    if (tid == 0) {
        float t = 0.f;
        #pragma unroll
        for (int i = 0; i < 8; i++) t += warp_s[i];
        float sc = t * (1.0f / 2048.0f);
        if (sc < 1e-5f) sc = 1e-5f;
        g_scale[row] = sc;
        s_scale = sc;
    }
    __syncthreads();
    const float sc = s_scale;

    float v[8] = {a.x, a.y, a.z, a.w, b.x, b.y, b.z, b.w};
    __half q[8];
    #pragma unroll
    for (int i = 0; i < 8; i++) {
        float t = rintf(v[i] / sc);              // matches jnp.round
        t = fmaxf(-1.f, fminf(1.f, t));
        q[i] = __float2half_rn(t);
    }
    *reinterpret_cast<uint4*>(g_Wq + (size_t)row * K_TOT + base) =
        *reinterpret_cast<uint4*>(q);
}

// ------------------------------ GEMM kernel --------------------------------
__global__ void __launch_bounds__(256, 2)
bitlinear_gemm(float* __restrict__ out) {
    extern __shared__ char smem[];
    const uint32_t sbase = smem_u32(smem);
    const int tid    = threadIdx.x;
    const int wid    = tid >> 5;
    const int lane   = tid & 31;
    const int warp_m = wid & 1;       // 2 warps along M
    const int warp_n = wid >> 1;      // 4 warps along N
    const int m0 = blockIdx.y * BM;
    const int n0 = blockIdx.x * BN;

    const __half* Ag = g_Xh + (size_t)m0 * K_TOT;
    const __half* Bg = g_Wq + (size_t)n0 * K_TOT;

    // copy mapping: tile = 128 rows x 8 segs(16B) = 1024 segs; 4 per thread
    auto issue_copy = [&](int stage, int chunk) {
        const int k0 = chunk * BK;
        uint32_t da = sbase + SMEM_A_OFF(stage);
        uint32_t db = sbase + SMEM_B_OFF(stage);
        #pragma unroll
        for (int j = 0; j < 4; j++) {
            int s = tid + 256 * j;
            int row = s >> 3, sg = s & 7;
            uint32_t off = row * SROWB + sg * 16;
            const __half* ga = Ag + (size_t)row * K_TOT + k0 + sg * 8;
            const __half* gb = Bg + (size_t)row * K_TOT + k0 + sg * 8;
            cp_async16(da + off, ga);
            cp_async16(db + off, gb);
        }
    };

    // ldmatrix per-thread address components
    const int aRow = warp_m * 64 + (lane & 15);        // + mt*16
    const int aCol = (lane >> 4) * 8;                  // + ks*16
    const int g    = lane >> 3;
    const int bRow = warp_n * 32 + ((g >> 1) << 3) + (lane & 7);  // + nt*16
    const int bCol = (g & 1) * 8;                      // + ks*16

    float acc[4][4][4];
    #pragma unroll
    for (int i = 0; i < 4; i++)
        #pragma unroll
        for (int j = 0; j < 4; j++)
            #pragma unroll
            for (int t = 0; t < 4; t++) acc[i][j][t] = 0.f;

    // prologue: stages 0..1
    #pragma unroll
    for (int s = 0; s < STAGES - 1; s++) {
        issue_copy(s, s);
        asm volatile("cp.async.commit_group;");
    }

    for (int c = 0; c < NUM_CHUNKS; c++) {
        asm volatile("cp.async.wait_group %0;" :: "n"(STAGES - 2));
        __syncthreads();

        const int nc = c + STAGES - 1;
        if (nc < NUM_CHUNKS) issue_copy(nc % STAGES, nc);
        asm volatile("cp.async.commit_group;");

        const int st = c % STAGES;
        const uint32_t sa = sbase + SMEM_A_OFF(st);
        const uint32_t sb = sbase + SMEM_B_OFF(st);

        #pragma unroll
        for (int ks = 0; ks < 4; ks++) {
            uint32_t af[4][4];
            #pragma unroll
            for (int mt = 0; mt < 4; mt++)
                ldsm_x4(sa + (aRow + mt * 16) * SROWB + (aCol + ks * 16) * 2,
                        af[mt]);
            uint32_t bf[2][4];
            #pragma unroll
            for (int nt = 0; nt < 2; nt++)
                ldsm_x4(sb + (bRow + nt * 16) * SROWB + (bCol + ks * 16) * 2,
                        bf[nt]);
            #pragma unroll
            for (int mi = 0; mi < 4; mi++)
                #pragma unroll
                for (int ni = 0; ni < 4; ni++)
                    mma16816(acc[mi][ni], af[mi],
                             bf[ni >> 1][(ni & 1) * 2],
                             bf[ni >> 1][(ni & 1) * 2 + 1]);
        }
    }

    // ---------------- epilogue: scale by g_scale[n], store fp32 ------------
    const int q = lane >> 2;          // row-in-8
    const int t = lane & 3;           // col-pair
    #pragma unroll
    for (int ni = 0; ni < 4; ni++) {
        const int n = n0 + warp_n * 32 + ni * 8 + t * 2;
        const float2 sc = *reinterpret_cast<const float2*>(&g_scale[n]);
        #pragma unroll
        for (int mi = 0; mi < 4; mi++) {
            const int m = m0 + warp_m * 64 + mi * 16 + q;
            float2 v0 = make_float2(acc[mi][ni][0] * sc.x, acc[mi][ni][1] * sc.y);
            float2 v1 = make_float2(acc[mi][ni][2] * sc.x, acc[mi][ni][3] * sc.y);
            *reinterpret_cast<float2*>(out + (size_t)m * N_TOT + n) = v0;
            *reinterpret_cast<float2*>(out + (size_t)(m + 8) * N_TOT + n) = v1;
        }
    }
}

// ------------------------------ launch -------------------------------------
extern "C" void kernel_launch(void* const* d_in, const int* in_sizes, int n_in,
                              void* d_out, int out_size) {
    const float* x = (const float*)d_in[0];      // [4,2048,2048]
    const float* w = (const float*)d_in[1];      // [8192,2048]
    float* out = (float*)d_out;                  // [4,2048,8192]

    cudaFuncSetAttribute(bitlinear_gemm,
                         cudaFuncAttributeMaxDynamicSharedMemorySize,
                         SMEM_TOTAL);

    convert_x_kernel<<<(M_TOT * K_TOT) / (256 * 8), 256>>>(x);
    quantize_w_kernel<<<N_TOT, 256>>>(w);

    dim3 grid(N_TOT / BN, M_TOT / BM);
    bitlinear_gemm<<<grid, 256, SMEM_TOTAL>>>(out);
}